// round 2
// baseline (speedup 1.0000x reference)
#include <cuda_runtime.h>

#define NL 32
#define DM 1024
#define NK 4
#define IQO 1024
#define IKV 256
#define IFF 2816

// Output row layout: row = (l*7 + mod)*8 + s*4 + k, columns = DM.
// MODULE_ORDER = [q, k, v, gate, up, o, down] -> mod 0..6.

__device__ __forceinline__ void ffma2(unsigned long long &d,
                                      unsigned long long a,
                                      unsigned long long b) {
    asm("fma.rn.f32x2 %0, %1, %2, %0;" : "+l"(d) : "l"(a), "l"(b));
}

__device__ __forceinline__ float pair_sum(unsigned long long v) {
    float lo, hi;
    asm("mov.b64 {%0, %1}, %2;" : "=f"(lo), "=f"(hi) : "l"(v));
    return lo + hi;
}

__device__ __forceinline__ unsigned long long dbits(double d) {
    return (unsigned long long)__double_as_longlong(d);
}

__device__ __forceinline__ float wsum(float v) {
    v += __shfl_xor_sync(0xffffffffu, v, 16);
    v += __shfl_xor_sync(0xffffffffu, v, 8);
    v += __shfl_xor_sync(0xffffffffu, v, 4);
    v += __shfl_xor_sync(0xffffffffu, v, 2);
    v += __shfl_xor_sync(0xffffffffu, v, 1);
    return v;
}

// ---- Affine module (q/k/v/o): proj[k,d] = sum_i x[k,i] * W[d,i], K=4 RHS ----
// 128 threads: 4 warps x 4 rows = 16 rows per block; 64 tiles/layer.
template <int I>
__device__ void affine_block(const float* __restrict__ xg,
                             const float* __restrict__ W,
                             float* __restrict__ out,
                             int l, int dt, int mod,
                             float4* xs4, int tid, int lane, int wid)
{
    // Stage x[4][I] into smem: I float4 total.
    const float4* xg4 = reinterpret_cast<const float4*>(xg) + (size_t)l * I;
    #pragma unroll
    for (int i = tid; i < I; i += 128) xs4[i] = xg4[i];
    __syncthreads();

    const int d0 = dt * 16 + wid * 4;
    const double2* w2 = reinterpret_cast<const double2*>(W) +
                        ((size_t)l * DM + d0) * (I / 4);
    const double2* xd = reinterpret_cast<const double2*>(xs4);

    unsigned long long acc[4][4];
    #pragma unroll
    for (int r = 0; r < 4; r++)
        #pragma unroll
        for (int k = 0; k < 4; k++) acc[r][k] = 0ull;

    #pragma unroll 2
    for (int c = lane; c < I / 4; c += 32) {
        double2 x0 = xd[c];
        double2 x1 = xd[(I / 4) + c];
        double2 x2 = xd[2 * (I / 4) + c];
        double2 x3 = xd[3 * (I / 4) + c];
        #pragma unroll
        for (int r = 0; r < 4; r++) {
            double2 w = __ldcs(w2 + r * (I / 4) + c);
            unsigned long long w01 = dbits(w.x), w23 = dbits(w.y);
            ffma2(acc[r][0], w01, dbits(x0.x)); ffma2(acc[r][0], w23, dbits(x0.y));
            ffma2(acc[r][1], w01, dbits(x1.x)); ffma2(acc[r][1], w23, dbits(x1.y));
            ffma2(acc[r][2], w01, dbits(x2.x)); ffma2(acc[r][2], w23, dbits(x2.y));
            ffma2(acc[r][3], w01, dbits(x3.x)); ffma2(acc[r][3], w23, dbits(x3.y));
        }
    }

    const int rowb = (l * 7 + mod) * 8 + 4;
    #pragma unroll
    for (int r = 0; r < 4; r++)
        #pragma unroll
        for (int k = 0; k < 4; k++) {
            float v = wsum(pair_sum(acc[r][k]));
            if (lane == (r * 4 + k)) out[(size_t)(rowb + k) * DM + d0 + r] = v;
        }
}

// ---- MLP module: gate/up/down share W_down -> 12 RHS, packed f32x2 FMA ----
// 128 threads: 4 warps x 4 rows = 16 rows per block; 64 tiles/layer.
__device__ void mlp_block(const float* __restrict__ cm,
                          const float* __restrict__ Wd,
                          float* __restrict__ out,
                          int l, int dt,
                          float4* xs4, int tid, int lane, int wid)
{
    const int d0 = dt * 16 + wid * 4;
    const float4*  xg4 = reinterpret_cast<const float4*>(cm) +
                         (size_t)l * 3 * NK * (IFF / 4);
    const double2* w2  = reinterpret_cast<const double2*>(Wd) +
                         ((size_t)l * DM + d0) * (IFF / 4);
    const double2* xd  = reinterpret_cast<const double2*>(xs4);

    unsigned long long acc[4][12];
    #pragma unroll
    for (int r = 0; r < 4; r++)
        #pragma unroll
        for (int j = 0; j < 12; j++) acc[r][j] = 0ull;

    // Chunking: 11 chunks of 64 f4 columns; per chunk stage 12 rows x 64 f4
    // = 768 float4 into double-buffered smem. Each thread stages 6 f4,
    // register-prefetched one chunk ahead.
    float4 pre[6];
    #pragma unroll
    for (int s = 0; s < 6; s++) {
        const int i = tid + s * 128;
        pre[s] = xg4[(i >> 6) * (IFF / 4) + (i & 63)];
    }

    for (int c = 0; c < 11; ++c) {
        float4* dst = xs4 + (c & 1) * 768;
        #pragma unroll
        for (int s = 0; s < 6; s++) dst[tid + s * 128] = pre[s];
        __syncthreads();
        if (c < 10) {
            #pragma unroll
            for (int s = 0; s < 6; s++) {
                const int i = tid + s * 128;
                pre[s] = xg4[(i >> 6) * (IFF / 4) + (c + 1) * 64 + (i & 63)];
            }
        }
        const double2* xb = xd + (c & 1) * 768;
        #pragma unroll
        for (int it = 0; it < 2; ++it) {
            const int cc = it * 32 + lane;
            const int wc = c * 64 + cc;
            double2 w0 = __ldcs(w2 + 0 * (IFF / 4) + wc);
            double2 w1 = __ldcs(w2 + 1 * (IFF / 4) + wc);
            double2 w2v = __ldcs(w2 + 2 * (IFF / 4) + wc);
            double2 w3 = __ldcs(w2 + 3 * (IFF / 4) + wc);
            const unsigned long long w0a = dbits(w0.x),  w0b = dbits(w0.y);
            const unsigned long long w1a = dbits(w1.x),  w1b = dbits(w1.y);
            const unsigned long long w2a = dbits(w2v.x), w2b = dbits(w2v.y);
            const unsigned long long w3a = dbits(w3.x),  w3b = dbits(w3.y);
            #pragma unroll
            for (int j = 0; j < 12; j++) {
                double2 xv = xb[j * 64 + cc];
                const unsigned long long xa = dbits(xv.x), xbb = dbits(xv.y);
                ffma2(acc[0][j], w0a, xa); ffma2(acc[0][j], w0b, xbb);
                ffma2(acc[1][j], w1a, xa); ffma2(acc[1][j], w1b, xbb);
                ffma2(acc[2][j], w2a, xa); ffma2(acc[2][j], w2b, xbb);
                ffma2(acc[3][j], w3a, xa); ffma2(acc[3][j], w3b, xbb);
            }
        }
    }

    // j = m*4 + k ; m=0 -> gate (mod 3), m=1 -> up (mod 4), m=2 -> down (mod 6)
    #pragma unroll
    for (int j = 0; j < 12; j++) {
        const int m = j >> 2;
        const int k = j & 3;
        const int mod = (m == 0) ? 3 : (m == 1) ? 4 : 6;
        const int rowb = (l * 7 + mod) * 8 + 4 + k;
        #pragma unroll
        for (int r = 0; r < 4; r++) {
            float v = wsum(pair_sum(acc[r][j]));
            if (lane == ((j * 4 + r) & 31)) out[(size_t)rowb * DM + d0 + r] = v;
        }
    }
}

__global__ __launch_bounds__(128, 3)
void bse_fused_kernel(const float* __restrict__ residual,
                      const float* __restrict__ cq,
                      const float* __restrict__ ck,
                      const float* __restrict__ cv,
                      const float* __restrict__ co,
                      const float* __restrict__ cm,
                      const float* __restrict__ Wq,
                      const float* __restrict__ Wk,
                      const float* __restrict__ Wv,
                      const float* __restrict__ Wo,
                      const float* __restrict__ Wd,
                      float* __restrict__ out)
{
    __shared__ float4 xs4[1536];   // 24 KB: MLP 2x768 f4; affine <=1024 f4
    const int bid = blockIdx.x;
    const int tid = threadIdx.x;
    const int lane = tid & 31;
    const int wid = tid >> 5;

    if (bid < 2048) {
        // W_down blocks first (longest-running)
        mlp_block(cm, Wd, out, bid >> 6, bid & 63, xs4, tid, lane, wid);
    } else if (bid < 4096) {
        const int a = bid - 2048;
        affine_block<IQO>(cq, Wq, out, a >> 6, a & 63, 0, xs4, tid, lane, wid);
    } else if (bid < 6144) {
        const int a = bid - 4096;
        affine_block<IQO>(co, Wo, out, a >> 6, a & 63, 5, xs4, tid, lane, wid);
    } else if (bid < 8192) {
        const int a = bid - 6144;
        affine_block<IKV>(ck, Wk, out, a >> 6, a & 63, 1, xs4, tid, lane, wid);
    } else if (bid < 10240) {
        const int a = bid - 8192;
        affine_block<IKV>(cv, Wv, out, a >> 6, a & 63, 2, xs4, tid, lane, wid);
    } else {
        // Residual copy: residual[l,mod,k,:] -> out row (g*8 + k)
        const float4* src = reinterpret_cast<const float4*>(residual);
        float4* dst = reinterpret_cast<float4*>(out);
        const int n = NL * 7 * NK * (DM / 4);          // 229376 float4
        for (int e = (bid - 10240) * 128 + tid; e < n; e += 512 * 128) {
            const int d = e & 255;
            const int k = (e >> 8) & 3;
            const int g = e >> 10;
            dst[(size_t)(g * 8 + k) * 256 + d] = __ldcs(src + e);
        }
    }
}

extern "C" void kernel_launch(void* const* d_in, const int* in_sizes, int n_in,
                              void* d_out, int out_size)
{
    (void)in_sizes; (void)n_in; (void)out_size;
    const float* residual = (const float*)d_in[0];
    const float* cq = (const float*)d_in[1];
    const float* ck = (const float*)d_in[2];
    const float* cv = (const float*)d_in[3];
    const float* co = (const float*)d_in[4];
    const float* cm = (const float*)d_in[5];
    const float* Wq = (const float*)d_in[6];
    const float* Wk = (const float*)d_in[7];
    const float* Wv = (const float*)d_in[8];
    const float* Wo = (const float*)d_in[9];
    const float* Wd = (const float*)d_in[10];
    float* out = (float*)d_out;

    bse_fused_kernel<<<10752, 128>>>(residual, cq, ck, cv, co, cm,
                                     Wq, Wk, Wv, Wo, Wd, out);
}

// round 3
// speedup vs baseline: 1.2287x; 1.2287x over previous
#include <cuda_runtime.h>

#define NL 32
#define DM 1024
#define NK 4
#define IQO 1024
#define IKV 256
#define IFF 2816

// Output row layout: row = (l*7 + mod)*8 + s*4 + k, columns = DM.
// MODULE_ORDER = [q, k, v, gate, up, o, down] -> mod 0..6.

__device__ __forceinline__ void ffma2(unsigned long long &d,
                                      unsigned long long a,
                                      unsigned long long b) {
    asm("fma.rn.f32x2 %0, %1, %2, %0;" : "+l"(d) : "l"(a), "l"(b));
}

__device__ __forceinline__ unsigned long long fdup(float f) {
    unsigned long long r;
    asm("mov.b64 %0, {%1, %1};" : "=l"(r) : "f"(f));
    return r;
}

__device__ __forceinline__ void unpack2(unsigned long long v, float &lo, float &hi) {
    asm("mov.b64 {%0, %1}, %2;" : "=f"(lo), "=f"(hi) : "l"(v));
}

__device__ __forceinline__ float getf(float4 v, int e) {
    return (e == 0) ? v.x : (e == 1) ? v.y : (e == 2) ? v.z : v.w;
}

__device__ __forceinline__ float wsum(float v) {
    v += __shfl_xor_sync(0xffffffffu, v, 16);
    v += __shfl_xor_sync(0xffffffffu, v, 8);
    v += __shfl_xor_sync(0xffffffffu, v, 4);
    v += __shfl_xor_sync(0xffffffffu, v, 2);
    v += __shfl_xor_sync(0xffffffffu, v, 1);
    return v;
}

// ---- Affine module (q/k/v/o): proj[k,d] = sum_i x[k,i] * W[d,i], K=4 RHS ----
// 256 threads: 8 warps x 4 rows = 32 rows per block; 32 tiles/layer.
// Smem layout: per float4-column cc, an 80B block holding 4 elems x 4 RHS
// interleaved: float idx = e*4 + k. One LDS.128 = all 4 RHS at elem e.
template <int I>
__device__ void affine_block(const float* __restrict__ xg,
                             const float* __restrict__ W,
                             float* __restrict__ out,
                             int l, int dt, int mod,
                             char* sm, int tid, int lane, int wid)
{
    const float4* xg4 = reinterpret_cast<const float4*>(xg) + (size_t)l * I;
    // Stage x interleaved: I float4 reads, scattered scalar STS.
    #pragma unroll
    for (int s = 0; s < I / 256; s++) {
        const int i = tid + s * 256;
        const int j = i / (I / 4);
        const int cc = i % (I / 4);
        float4 v = xg4[(size_t)j * (I / 4) + cc];
        float* dst = reinterpret_cast<float*>(sm + cc * 80);
        dst[0 * 4 + j] = v.x;
        dst[1 * 4 + j] = v.y;
        dst[2 * 4 + j] = v.z;
        dst[3 * 4 + j] = v.w;
    }
    __syncthreads();

    const int d0 = dt * 32 + wid * 4;
    const float4* w4 = reinterpret_cast<const float4*>(W) +
                       ((size_t)l * DM + d0) * (I / 4);

    unsigned long long acc[4][2];
    #pragma unroll
    for (int r = 0; r < 4; r++) { acc[r][0] = 0ull; acc[r][1] = 0ull; }

    #pragma unroll 2
    for (int c = lane; c < I / 4; c += 32) {
        float4 w0 = __ldcs(w4 + 0 * (I / 4) + c);
        float4 w1 = __ldcs(w4 + 1 * (I / 4) + c);
        float4 w2 = __ldcs(w4 + 2 * (I / 4) + c);
        float4 w3 = __ldcs(w4 + 3 * (I / 4) + c);
        const char* xp = sm + c * 80;
        #pragma unroll
        for (int e = 0; e < 4; e++) {
            ulonglong2 xv = *reinterpret_cast<const ulonglong2*>(xp + e * 16);
            unsigned long long d0d = fdup(getf(w0, e));
            unsigned long long d1d = fdup(getf(w1, e));
            unsigned long long d2d = fdup(getf(w2, e));
            unsigned long long d3d = fdup(getf(w3, e));
            ffma2(acc[0][0], d0d, xv.x); ffma2(acc[0][1], d0d, xv.y);
            ffma2(acc[1][0], d1d, xv.x); ffma2(acc[1][1], d1d, xv.y);
            ffma2(acc[2][0], d2d, xv.x); ffma2(acc[2][1], d2d, xv.y);
            ffma2(acc[3][0], d3d, xv.x); ffma2(acc[3][1], d3d, xv.y);
        }
    }

    const int rowb = (l * 7 + mod) * 8 + 4;
    #pragma unroll
    for (int r = 0; r < 4; r++)
        #pragma unroll
        for (int q = 0; q < 2; q++) {
            float lo, hi;
            unpack2(acc[r][q], lo, hi);
            float vlo = wsum(lo);
            float vhi = wsum(hi);
            const int k0 = 2 * q, k1 = 2 * q + 1;
            if (lane == (r * 4 + k0)) out[(size_t)(rowb + k0) * DM + d0 + r] = vlo;
            if (lane == (r * 4 + k1)) out[(size_t)(rowb + k1) * DM + d0 + r] = vhi;
        }
}

// ---- MLP module: gate/up/down share W_down -> 12 RHS, RHS-packed f32x2 ----
// 256 threads: 8 warps x 4 rows = 32 rows per block; 32 tiles/layer.
// Per chunk (64 float4 cols): per col cc a 208B block: float idx =
// (e*3 + (j>>2))*4 + (j&3). One LDS.128 at (e*3+p)*16 = RHS 4p..4p+3, elem e.
__device__ void mlp_block(const float* __restrict__ cm,
                          const float* __restrict__ Wd,
                          float* __restrict__ out,
                          int l, int dt,
                          char* sm, int tid, int lane, int wid)
{
    const int d0 = dt * 32 + wid * 4;
    const float4* xg4 = reinterpret_cast<const float4*>(cm) +
                        (size_t)l * 3 * NK * (IFF / 4);
    const float4* w4  = reinterpret_cast<const float4*>(Wd) +
                        ((size_t)l * DM + d0) * (IFF / 4);

    unsigned long long acc[4][6];
    #pragma unroll
    for (int r = 0; r < 4; r++)
        #pragma unroll
        for (int q = 0; q < 6; q++) acc[r][q] = 0ull;

    // Each chunk stages 12 rows x 64 float4 = 768 float4; 3 per thread.
    float4 pre[3];
    #pragma unroll
    for (int s = 0; s < 3; s++) {
        const int i = tid + s * 256;
        pre[s] = xg4[(size_t)(i >> 6) * (IFF / 4) + (i & 63)];
    }

    for (int c = 0; c < 11; ++c) {
        char* buf = sm + (c & 1) * 13312;
        #pragma unroll
        for (int s = 0; s < 3; s++) {
            const int i = tid + s * 256;
            const int j = i >> 6;
            const int cc = i & 63;
            const int jq = j >> 2, jr = j & 3;
            float* dst = reinterpret_cast<float*>(buf + cc * 208);
            dst[(0 * 3 + jq) * 4 + jr] = pre[s].x;
            dst[(1 * 3 + jq) * 4 + jr] = pre[s].y;
            dst[(2 * 3 + jq) * 4 + jr] = pre[s].z;
            dst[(3 * 3 + jq) * 4 + jr] = pre[s].w;
        }
        __syncthreads();
        if (c < 10) {
            #pragma unroll
            for (int s = 0; s < 3; s++) {
                const int i = tid + s * 256;
                pre[s] = xg4[(size_t)(i >> 6) * (IFF / 4) + (c + 1) * 64 + (i & 63)];
            }
        }
        #pragma unroll
        for (int it = 0; it < 2; ++it) {
            const int cc = it * 32 + lane;
            const int wc = c * 64 + cc;
            float4 w0 = __ldcs(w4 + 0 * (IFF / 4) + wc);
            float4 w1 = __ldcs(w4 + 1 * (IFF / 4) + wc);
            float4 w2 = __ldcs(w4 + 2 * (IFF / 4) + wc);
            float4 w3 = __ldcs(w4 + 3 * (IFF / 4) + wc);
            const char* xp = buf + cc * 208;
            #pragma unroll
            for (int e = 0; e < 4; e++) {
                ulonglong2 p0 = *reinterpret_cast<const ulonglong2*>(xp + (e * 3 + 0) * 16);
                ulonglong2 p1 = *reinterpret_cast<const ulonglong2*>(xp + (e * 3 + 1) * 16);
                ulonglong2 p2 = *reinterpret_cast<const ulonglong2*>(xp + (e * 3 + 2) * 16);
                unsigned long long d0d = fdup(getf(w0, e));
                unsigned long long d1d = fdup(getf(w1, e));
                unsigned long long d2d = fdup(getf(w2, e));
                unsigned long long d3d = fdup(getf(w3, e));
                ffma2(acc[0][0], d0d, p0.x); ffma2(acc[0][1], d0d, p0.y);
                ffma2(acc[0][2], d0d, p1.x); ffma2(acc[0][3], d0d, p1.y);
                ffma2(acc[0][4], d0d, p2.x); ffma2(acc[0][5], d0d, p2.y);
                ffma2(acc[1][0], d1d, p0.x); ffma2(acc[1][1], d1d, p0.y);
                ffma2(acc[1][2], d1d, p1.x); ffma2(acc[1][3], d1d, p1.y);
                ffma2(acc[1][4], d1d, p2.x); ffma2(acc[1][5], d1d, p2.y);
                ffma2(acc[2][0], d2d, p0.x); ffma2(acc[2][1], d2d, p0.y);
                ffma2(acc[2][2], d2d, p1.x); ffma2(acc[2][3], d2d, p1.y);
                ffma2(acc[2][4], d2d, p2.x); ffma2(acc[2][5], d2d, p2.y);
                ffma2(acc[3][0], d3d, p0.x); ffma2(acc[3][1], d3d, p0.y);
                ffma2(acc[3][2], d3d, p1.x); ffma2(acc[3][3], d3d, p1.y);
                ffma2(acc[3][4], d3d, p2.x); ffma2(acc[3][5], d3d, p2.y);
            }
        }
        __syncthreads();
    }

    // acc[r][q]: lo -> j=2q, hi -> j=2q+1; j = m*4 + k,
    // m=0 -> gate (mod 3), m=1 -> up (mod 4), m=2 -> down (mod 6)
    #pragma unroll
    for (int q = 0; q < 6; q++) {
        #pragma unroll
        for (int r = 0; r < 4; r++) {
            float lo, hi;
            unpack2(acc[r][q], lo, hi);
            float vlo = wsum(lo);
            float vhi = wsum(hi);
            #pragma unroll
            for (int h = 0; h < 2; h++) {
                const int j = 2 * q + h;
                const int m = j >> 2;
                const int k = j & 3;
                const int mod = (m == 0) ? 3 : (m == 1) ? 4 : 6;
                const int rowb = (l * 7 + mod) * 8 + 4 + k;
                const float v = h ? vhi : vlo;
                if (lane == ((j * 4 + r) & 31))
                    out[(size_t)rowb * DM + d0 + r] = v;
            }
        }
    }
}

__global__ __launch_bounds__(256, 2)
void bse_fused_kernel(const float* __restrict__ residual,
                      const float* __restrict__ cq,
                      const float* __restrict__ ck,
                      const float* __restrict__ cv,
                      const float* __restrict__ co,
                      const float* __restrict__ cm,
                      const float* __restrict__ Wq,
                      const float* __restrict__ Wk,
                      const float* __restrict__ Wv,
                      const float* __restrict__ Wo,
                      const float* __restrict__ Wd,
                      float* __restrict__ out)
{
    // MLP: 2 x 13312 B double buffer. Affine: up to 256*80 = 20480 B.
    __shared__ __align__(16) char sm[26624];
    const int bid = blockIdx.x;
    const int tid = threadIdx.x;
    const int lane = tid & 31;
    const int wid = tid >> 5;

    if (bid < 1024) {
        mlp_block(cm, Wd, out, bid >> 5, bid & 31, sm, tid, lane, wid);
    } else if (bid < 2048) {
        const int a = bid - 1024;
        affine_block<IQO>(cq, Wq, out, a >> 5, a & 31, 0, sm, tid, lane, wid);
    } else if (bid < 3072) {
        const int a = bid - 2048;
        affine_block<IQO>(co, Wo, out, a >> 5, a & 31, 5, sm, tid, lane, wid);
    } else if (bid < 4096) {
        const int a = bid - 3072;
        affine_block<IKV>(ck, Wk, out, a >> 5, a & 31, 1, sm, tid, lane, wid);
    } else if (bid < 5120) {
        const int a = bid - 4096;
        affine_block<IKV>(cv, Wv, out, a >> 5, a & 31, 2, sm, tid, lane, wid);
    } else {
        // Residual copy: residual[l,mod,k,:] -> out row (g*8 + k)
        const float4* src = reinterpret_cast<const float4*>(residual);
        float4* dst = reinterpret_cast<float4*>(out);
        const int n = NL * 7 * NK * (DM / 4);          // 229376 float4
        for (int e = (bid - 5120) * 256 + tid; e < n; e += 512 * 256) {
            const int d = e & 255;
            const int k = (e >> 8) & 3;
            const int g = e >> 10;
            dst[(size_t)(g * 8 + k) * 256 + d] = __ldcs(src + e);
        }
    }
}

extern "C" void kernel_launch(void* const* d_in, const int* in_sizes, int n_in,
                              void* d_out, int out_size)
{
    (void)in_sizes; (void)n_in; (void)out_size;
    const float* residual = (const float*)d_in[0];
    const float* cq = (const float*)d_in[1];
    const float* ck = (const float*)d_in[2];
    const float* cv = (const float*)d_in[3];
    const float* co = (const float*)d_in[4];
    const float* cm = (const float*)d_in[5];
    const float* Wq = (const float*)d_in[6];
    const float* Wk = (const float*)d_in[7];
    const float* Wv = (const float*)d_in[8];
    const float* Wo = (const float*)d_in[9];
    const float* Wd = (const float*)d_in[10];
    float* out = (float*)d_out;

    bse_fused_kernel<<<5632, 256>>>(residual, cq, ck, cv, co, cm,
                                    Wq, Wk, Wv, Wo, Wd, out);
}

// round 5
// speedup vs baseline: 1.2455x; 1.0137x over previous
#include <cuda_runtime.h>
#include <cstdint>

#define NL 32
#define DM 1024
#define NK 4
#define IQO 1024
#define IKV 256
#define IFF 2816

// -------- device scratch: pre-transposed x (RHS-interleaved) --------
// xt_mlp quad (l*IFF + i)*3 + p : floats j = 4p..4p+3 at element i (j = m*4+k)
// xt_q   quad (l*IQO + i)      : floats k = 0..3 at element i
__device__ float4 g_xt_mlp[NL * IFF * 3];
__device__ float4 g_xt_q[NL * IQO];
__device__ float4 g_xt_k[NL * IKV];
__device__ float4 g_xt_v[NL * IKV];
__device__ float4 g_xt_o[NL * IQO];

__global__ void transpose_x_kernel(const float* __restrict__ cq,
                                   const float* __restrict__ ck,
                                   const float* __restrict__ cv,
                                   const float* __restrict__ co,
                                   const float* __restrict__ cm)
{
    const int stride = gridDim.x * blockDim.x;
    const int t0 = blockIdx.x * blockDim.x + threadIdx.x;

    for (int e = t0; e < NL * IFF; e += stride) {
        const int l = e / IFF, i = e % IFF;
        const float* src = cm + (size_t)l * 12 * IFF + i;
        float v[12];
        #pragma unroll
        for (int j = 0; j < 12; j++) v[j] = src[(size_t)j * IFF];
        float4* dst = &g_xt_mlp[(size_t)e * 3];
        dst[0] = make_float4(v[0], v[1], v[2], v[3]);
        dst[1] = make_float4(v[4], v[5], v[6], v[7]);
        dst[2] = make_float4(v[8], v[9], v[10], v[11]);
    }
    for (int e = t0; e < NL * IQO; e += stride) {
        const int l = e / IQO, i = e % IQO;
        const float* sq = cq + (size_t)l * 4 * IQO + i;
        const float* so = co + (size_t)l * 4 * IQO + i;
        g_xt_q[e] = make_float4(sq[0], sq[IQO], sq[2 * IQO], sq[3 * IQO]);
        g_xt_o[e] = make_float4(so[0], so[IQO], so[2 * IQO], so[3 * IQO]);
    }
    for (int e = t0; e < NL * IKV; e += stride) {
        const int l = e / IKV, i = e % IKV;
        const float* sk = ck + (size_t)l * 4 * IKV + i;
        const float* sv = cv + (size_t)l * 4 * IKV + i;
        g_xt_k[e] = make_float4(sk[0], sk[IKV], sk[2 * IKV], sk[3 * IKV]);
        g_xt_v[e] = make_float4(sv[0], sv[IKV], sv[2 * IKV], sv[3 * IKV]);
    }
}

// -------- PTX helpers --------
__device__ __forceinline__ void ffma2(unsigned long long &d,
                                      unsigned long long a,
                                      unsigned long long b) {
    asm("fma.rn.f32x2 %0, %1, %2, %0;" : "+l"(d) : "l"(a), "l"(b));
}
__device__ __forceinline__ unsigned long long fdup(float f) {
    unsigned long long r;
    asm("mov.b64 %0, {%1, %1};" : "=l"(r) : "f"(f));
    return r;
}
__device__ __forceinline__ void unpack2(unsigned long long v, float &lo, float &hi) {
    asm("mov.b64 {%0, %1}, %2;" : "=f"(lo), "=f"(hi) : "l"(v));
}
__device__ __forceinline__ float getf(float4 v, int e) {
    return (e == 0) ? v.x : (e == 1) ? v.y : (e == 2) ? v.z : v.w;
}
__device__ __forceinline__ float wsum(float v) {
    v += __shfl_xor_sync(0xffffffffu, v, 16);
    v += __shfl_xor_sync(0xffffffffu, v, 8);
    v += __shfl_xor_sync(0xffffffffu, v, 4);
    v += __shfl_xor_sync(0xffffffffu, v, 2);
    v += __shfl_xor_sync(0xffffffffu, v, 1);
    return v;
}
__device__ __forceinline__ void cpasync16(uint32_t dst, const void* src) {
    asm volatile("cp.async.cg.shared.global [%0], [%1], 16;" :: "r"(dst), "l"(src));
}
#define CP_COMMIT() asm volatile("cp.async.commit_group;" ::: "memory")
template <int N>
__device__ __forceinline__ void cp_wait() {
    asm volatile("cp.async.wait_group %0;" :: "n"(N) : "memory");
}

// ---- Affine module (q/k/v/o): 256 thr, 8 warps x 4 rows = 32 rows/block ----
// Smem: per f4-column cc an 80B block (5 quads): quad e = x[k0..k3] at elem
// i = cc*4+e. LDS.128 stride 5 quads -> conflict-free.
template <int I>
__device__ void affine_block(const float4* __restrict__ xt,
                             const float* __restrict__ W,
                             float* __restrict__ out,
                             int l, int dt, int mod,
                             char* sm, uint32_t smem_u,
                             int tid, int lane, int wid)
{
    // Stage x via cp.async: quad seg -> cc = seg>>2, e = seg&3
    const float4* src = xt + (size_t)l * I;
    #pragma unroll
    for (int s = 0; s < I / 256; s++) {
        const int seg = tid + s * 256;
        cpasync16(smem_u + (seg >> 2) * 80 + (seg & 3) * 16, src + seg);
    }
    CP_COMMIT();
    cp_wait<0>();
    __syncthreads();

    const int d0 = dt * 32 + wid * 4;
    const float4* w4 = reinterpret_cast<const float4*>(W) +
                       ((size_t)l * DM + d0) * (I / 4);

    unsigned long long acc[4][2];
    #pragma unroll
    for (int r = 0; r < 4; r++) { acc[r][0] = 0ull; acc[r][1] = 0ull; }

    #pragma unroll 2
    for (int c = lane; c < I / 4; c += 32) {
        float4 w0 = __ldcs(w4 + 0 * (I / 4) + c);
        float4 w1 = __ldcs(w4 + 1 * (I / 4) + c);
        float4 w2 = __ldcs(w4 + 2 * (I / 4) + c);
        float4 w3 = __ldcs(w4 + 3 * (I / 4) + c);
        const char* xp = sm + c * 80;
        #pragma unroll
        for (int e = 0; e < 4; e++) {
            ulonglong2 xv = *reinterpret_cast<const ulonglong2*>(xp + e * 16);
            unsigned long long d0d = fdup(getf(w0, e));
            unsigned long long d1d = fdup(getf(w1, e));
            unsigned long long d2d = fdup(getf(w2, e));
            unsigned long long d3d = fdup(getf(w3, e));
            ffma2(acc[0][0], d0d, xv.x); ffma2(acc[0][1], d0d, xv.y);
            ffma2(acc[1][0], d1d, xv.x); ffma2(acc[1][1], d1d, xv.y);
            ffma2(acc[2][0], d2d, xv.x); ffma2(acc[2][1], d2d, xv.y);
            ffma2(acc[3][0], d3d, xv.x); ffma2(acc[3][1], d3d, xv.y);
        }
    }

    const int rowb = (l * 7 + mod) * 8 + 4;
    #pragma unroll
    for (int r = 0; r < 4; r++)
        #pragma unroll
        for (int q = 0; q < 2; q++) {
            float lo, hi;
            unpack2(acc[r][q], lo, hi);
            float vlo = wsum(lo);
            float vhi = wsum(hi);
            const int k0 = 2 * q, k1 = 2 * q + 1;
            if (lane == (r * 4 + k0)) out[(size_t)(rowb + k0) * DM + d0 + r] = vlo;
            if (lane == (r * 4 + k1)) out[(size_t)(rowb + k1) * DM + d0 + r] = vhi;
        }
}

// ---- MLP module: 12 RHS share W_down; 256 thr, 8 warps x 4 rows ----
// Chunks of 64 f4 cols; per col cc a 208B block (13 quads): quad (e*3+p) =
// x[j=4p..4p+3] at elem i = (c*64+cc)*4+e. Triple-buffered cp.async staging.
#define MBUF 13312     // 64 * 208
__device__ void mlp_block(const float* __restrict__ Wd,
                          float* __restrict__ out,
                          int l, int dt,
                          char* sm, uint32_t smem_u,
                          int tid, int lane, int wid)
{
    const int d0 = dt * 32 + wid * 4;
    const float4* xt = g_xt_mlp + (size_t)l * IFF * 3;   // quad base for layer
    const float4* w4 = reinterpret_cast<const float4*>(Wd) +
                       ((size_t)l * DM + d0) * (IFF / 4);

    unsigned long long acc[4][6];
    #pragma unroll
    for (int r = 0; r < 4; r++)
        #pragma unroll
        for (int q = 0; q < 6; q++) acc[r][q] = 0ull;

    // stage chunk c into buffer b: 768 quads; seg -> cc = seg/12, q = seg%12
    auto stage = [&](int c, int b) {
        const float4* src = xt + c * 768;
        const uint32_t dbase = smem_u + b * MBUF;
        #pragma unroll
        for (int s = 0; s < 3; s++) {
            const int seg = tid + s * 256;
            const int cc = seg / 12, q = seg - cc * 12;
            cpasync16(dbase + cc * 208 + q * 16, src + seg);
        }
        CP_COMMIT();
    };

    stage(0, 0);
    stage(1, 1);

    for (int c = 0; c < 11; c++) {
        if (c < 10) cp_wait<1>(); else cp_wait<0>();
        __syncthreads();
        if (c + 2 < 11) stage(c + 2, (c + 2) % 3);

        const char* buf = sm + (c % 3) * MBUF;
        #pragma unroll
        for (int it = 0; it < 2; ++it) {
            const int cc = it * 32 + lane;
            const int wc = c * 64 + cc;
            float4 w0 = __ldcs(w4 + 0 * (IFF / 4) + wc);
            float4 w1 = __ldcs(w4 + 1 * (IFF / 4) + wc);
            float4 w2 = __ldcs(w4 + 2 * (IFF / 4) + wc);
            float4 w3 = __ldcs(w4 + 3 * (IFF / 4) + wc);
            const char* xp = buf + cc * 208;
            #pragma unroll
            for (int e = 0; e < 4; e++) {
                ulonglong2 p0 = *reinterpret_cast<const ulonglong2*>(xp + (e * 3 + 0) * 16);
                ulonglong2 p1 = *reinterpret_cast<const ulonglong2*>(xp + (e * 3 + 1) * 16);
                ulonglong2 p2 = *reinterpret_cast<const ulonglong2*>(xp + (e * 3 + 2) * 16);
                unsigned long long d0d = fdup(getf(w0, e));
                unsigned long long d1d = fdup(getf(w1, e));
                unsigned long long d2d = fdup(getf(w2, e));
                unsigned long long d3d = fdup(getf(w3, e));
                ffma2(acc[0][0], d0d, p0.x); ffma2(acc[0][1], d0d, p0.y);
                ffma2(acc[0][2], d0d, p1.x); ffma2(acc[0][3], d0d, p1.y);
                ffma2(acc[0][4], d0d, p2.x); ffma2(acc[0][5], d0d, p2.y);
                ffma2(acc[1][0], d1d, p0.x); ffma2(acc[1][1], d1d, p0.y);
                ffma2(acc[1][2], d1d, p1.x); ffma2(acc[1][3], d1d, p1.y);
                ffma2(acc[1][4], d1d, p2.x); ffma2(acc[1][5], d1d, p2.y);
                ffma2(acc[2][0], d2d, p0.x); ffma2(acc[2][1], d2d, p0.y);
                ffma2(acc[2][2], d2d, p1.x); ffma2(acc[2][3], d2d, p1.y);
                ffma2(acc[2][4], d2d, p2.x); ffma2(acc[2][5], d2d, p2.y);
                ffma2(acc[3][0], d3d, p0.x); ffma2(acc[3][1], d3d, p0.y);
                ffma2(acc[3][2], d3d, p1.x); ffma2(acc[3][3], d3d, p1.y);
                ffma2(acc[3][4], d3d, p2.x); ffma2(acc[3][5], d3d, p2.y);
            }
        }
    }

    // acc[r][q]: lo -> j=2q, hi -> j=2q+1; j = m*4+k; m: 0->gate(3),1->up(4),2->down(6)
    #pragma unroll
    for (int q = 0; q < 6; q++) {
        #pragma unroll
        for (int r = 0; r < 4; r++) {
            float lo, hi;
            unpack2(acc[r][q], lo, hi);
            float vlo = wsum(lo);
            float vhi = wsum(hi);
            #pragma unroll
            for (int h = 0; h < 2; h++) {
                const int j = 2 * q + h;
                const int m = j >> 2;
                const int k = j & 3;
                const int mod = (m == 0) ? 3 : (m == 1) ? 4 : 6;
                const int rowb = (l * 7 + mod) * 8 + 4 + k;
                const float v = h ? vhi : vlo;
                if (lane == ((j * 4 + r) & 31))
                    out[(size_t)rowb * DM + d0 + r] = v;
            }
        }
    }
}

__global__ __launch_bounds__(256, 2)
void bse_fused_kernel(const float* __restrict__ residual,
                      const float* __restrict__ Wq,
                      const float* __restrict__ Wk,
                      const float* __restrict__ Wv,
                      const float* __restrict__ Wo,
                      const float* __restrict__ Wd,
                      float* __restrict__ out)
{
    __shared__ __align__(16) char sm[3 * MBUF];   // 39936 B
    const int bid = blockIdx.x;
    const int tid = threadIdx.x;
    const int lane = tid & 31;
    const int wid = tid >> 5;
    const uint32_t smem_u = (uint32_t)__cvta_generic_to_shared(sm);

    if (bid < 1024) {
        mlp_block(Wd, out, bid >> 5, bid & 31, sm, smem_u, tid, lane, wid);
    } else if (bid < 2048) {
        const int a = bid - 1024;
        affine_block<IQO>(g_xt_q, Wq, out, a >> 5, a & 31, 0, sm, smem_u, tid, lane, wid);
    } else if (bid < 3072) {
        const int a = bid - 2048;
        affine_block<IQO>(g_xt_o, Wo, out, a >> 5, a & 31, 5, sm, smem_u, tid, lane, wid);
    } else if (bid < 4096) {
        const int a = bid - 3072;
        affine_block<IKV>(g_xt_k, Wk, out, a >> 5, a & 31, 1, sm, smem_u, tid, lane, wid);
    } else if (bid < 5120) {
        const int a = bid - 4096;
        affine_block<IKV>(g_xt_v, Wv, out, a >> 5, a & 31, 2, sm, smem_u, tid, lane, wid);
    } else {
        // Residual copy: residual[l,mod,k,:] -> out row (g*8 + k)
        const float4* src = reinterpret_cast<const float4*>(residual);
        float4* dst = reinterpret_cast<float4*>(out);
        const int n = NL * 7 * NK * (DM / 4);          // 229376 float4
        for (int e = (bid - 5120) * 256 + tid; e < n; e += 512 * 256) {
            const int d = e & 255;
            const int k = (e >> 8) & 3;
            const int g = e >> 10;
            dst[(size_t)(g * 8 + k) * 256 + d] = __ldcs(src + e);
        }
    }
}

extern "C" void kernel_launch(void* const* d_in, const int* in_sizes, int n_in,
                              void* d_out, int out_size)
{
    (void)in_sizes; (void)n_in; (void)out_size;
    const float* residual = (const float*)d_in[0];
    const float* cq = (const float*)d_in[1];
    const float* ck = (const float*)d_in[2];
    const float* cv = (const float*)d_in[3];
    const float* co = (const float*)d_in[4];
    const float* cm = (const float*)d_in[5];
    const float* Wq = (const float*)d_in[6];
    const float* Wk = (const float*)d_in[7];
    const float* Wv = (const float*)d_in[8];
    const float* Wo = (const float*)d_in[9];
    const float* Wd = (const float*)d_in[10];
    float* out = (float*)d_out;

    transpose_x_kernel<<<512, 256>>>(cq, ck, cv, co, cm);
    bse_fused_kernel<<<5632, 256>>>(residual, Wq, Wk, Wv, Wo, Wd, out);
}

// round 6
// speedup vs baseline: 1.2674x; 1.0176x over previous
#include <cuda_runtime.h>
#include <cstdint>

#define NL 32
#define DM 1024
#define NK 4
#define IQO 1024
#define IKV 256
#define IFF 2816

#define KCH 128                    // K floats per pipeline chunk
#define MLP_C (IFF / KCH)          // 22
#define QO_C  (IQO / KCH)          // 8
#define KV_C  (IKV / KCH)          // 2

#define W_BYTES (32 * KCH * 4)     // 16384 per chunk (32 rows x 512 B)
#define XM_Q 416                   // mlp x quads per chunk (32 cc x 13)
#define XA_Q 160                   // affine x quads per chunk (32 cc x 5)
#define MSTG (W_BYTES + XM_Q * 16) // 23040
#define ASTG (W_BYTES + XA_Q * 16) // 18944
#define SMEM_BYTES (4 * MSTG)      // 92160

// -------- pre-transposed x scratch (written by prologue kernel) --------
// mlp: quad ((l*22 + c)*32 + cc)*13 + e*3 + p  = x[j=4p..4p+3] at elem (c*32+cc)*4+e
// aff: quad ((l*C  + c)*32 + cc)*5  + e        = x[k=0..3]     at elem (c*32+cc)*4+e
__device__ float4 g_xt_mlp[NL * MLP_C * XM_Q];
__device__ float4 g_xt_q[NL * QO_C * XA_Q];
__device__ float4 g_xt_o[NL * QO_C * XA_Q];
__device__ float4 g_xt_k[NL * KV_C * XA_Q];
__device__ float4 g_xt_v[NL * KV_C * XA_Q];

__global__ void transpose_x_kernel(const float* __restrict__ cq,
                                   const float* __restrict__ ck,
                                   const float* __restrict__ cv,
                                   const float* __restrict__ co,
                                   const float* __restrict__ cm)
{
    const int stride = gridDim.x * blockDim.x;
    const int t0 = blockIdx.x * blockDim.x + threadIdx.x;

    for (int eidx = t0; eidx < NL * IFF; eidx += stride) {
        const int l = eidx / IFF, i = eidx % IFF;
        const int c = i >> 7, cc = (i >> 2) & 31, e = i & 3;
        const float* src = cm + (size_t)l * 12 * IFF + i;
        float v[12];
        #pragma unroll
        for (int j = 0; j < 12; j++) v[j] = src[(size_t)j * IFF];
        float4* dst = &g_xt_mlp[((size_t)(l * MLP_C + c) * 32 + cc) * 13 + e * 3];
        dst[0] = make_float4(v[0], v[1], v[2], v[3]);
        dst[1] = make_float4(v[4], v[5], v[6], v[7]);
        dst[2] = make_float4(v[8], v[9], v[10], v[11]);
    }
    for (int eidx = t0; eidx < NL * IQO; eidx += stride) {
        const int l = eidx / IQO, i = eidx % IQO;
        const int c = i >> 7, cc = (i >> 2) & 31, e = i & 3;
        const size_t qi = ((size_t)(l * QO_C + c) * 32 + cc) * 5 + e;
        const float* sq = cq + (size_t)l * 4 * IQO + i;
        const float* so = co + (size_t)l * 4 * IQO + i;
        g_xt_q[qi] = make_float4(sq[0], sq[IQO], sq[2 * IQO], sq[3 * IQO]);
        g_xt_o[qi] = make_float4(so[0], so[IQO], so[2 * IQO], so[3 * IQO]);
    }
    for (int eidx = t0; eidx < NL * IKV; eidx += stride) {
        const int l = eidx / IKV, i = eidx % IKV;
        const int c = i >> 7, cc = (i >> 2) & 31, e = i & 3;
        const size_t qi = ((size_t)(l * KV_C + c) * 32 + cc) * 5 + e;
        const float* sk = ck + (size_t)l * 4 * IKV + i;
        const float* sv = cv + (size_t)l * 4 * IKV + i;
        g_xt_k[qi] = make_float4(sk[0], sk[IKV], sk[2 * IKV], sk[3 * IKV]);
        g_xt_v[qi] = make_float4(sv[0], sv[IKV], sv[2 * IKV], sv[3 * IKV]);
    }
}

// -------- PTX helpers --------
__device__ __forceinline__ void ffma2(unsigned long long &d,
                                      unsigned long long a,
                                      unsigned long long b) {
    asm("fma.rn.f32x2 %0, %1, %2, %0;" : "+l"(d) : "l"(a), "l"(b));
}
__device__ __forceinline__ unsigned long long fdup(float f) {
    unsigned long long r;
    asm("mov.b64 %0, {%1, %1};" : "=l"(r) : "f"(f));
    return r;
}
__device__ __forceinline__ void unpack2(unsigned long long v, float &lo, float &hi) {
    asm("mov.b64 {%0, %1}, %2;" : "=f"(lo), "=f"(hi) : "l"(v));
}
__device__ __forceinline__ float getf(float4 v, int e) {
    return (e == 0) ? v.x : (e == 1) ? v.y : (e == 2) ? v.z : v.w;
}
__device__ __forceinline__ float wsum(float v) {
    v += __shfl_xor_sync(0xffffffffu, v, 16);
    v += __shfl_xor_sync(0xffffffffu, v, 8);
    v += __shfl_xor_sync(0xffffffffu, v, 4);
    v += __shfl_xor_sync(0xffffffffu, v, 2);
    v += __shfl_xor_sync(0xffffffffu, v, 1);
    return v;
}
__device__ __forceinline__ void cpasync16(uint32_t dst, const void* src) {
    asm volatile("cp.async.cg.shared.global [%0], [%1], 16;" :: "r"(dst), "l"(src));
}
#define CP_COMMIT() asm volatile("cp.async.commit_group;" ::: "memory")
template <int N>
__device__ __forceinline__ void cp_wait() {
    asm volatile("cp.async.wait_group %0;" :: "n"(N) : "memory");
}
__device__ __forceinline__ void pipeline_wait(int pend) {
    if (pend >= 2) cp_wait<2>();
    else if (pend == 1) cp_wait<1>();
    else cp_wait<0>();
}

// ---- MLP module: 12 RHS share W_down; 256 thr, 8 warps x 4 rows = 32 rows ----
__device__ void mlp_block(const float* __restrict__ Wd,
                          float* __restrict__ out,
                          int l, int dt,
                          char* sm, uint32_t smem_u,
                          int tid, int lane, int wid)
{
    const float* Wg = Wd + ((size_t)l * DM + dt * 32) * IFF;
    const float4* xs = g_xt_mlp + (size_t)l * MLP_C * XM_Q;

    unsigned long long acc[4][6];
    #pragma unroll
    for (int r = 0; r < 4; r++)
        #pragma unroll
        for (int q = 0; q < 6; q++) acc[r][q] = 0ull;

    auto stage = [&](int c) {
        const uint32_t buf = smem_u + (c & 3) * MSTG;
        const float* wsrc = Wg + c * KCH;
        #pragma unroll
        for (int s = 0; s < 4; s++) {
            const int seg = tid + s * 256;
            cpasync16(buf + seg * 16,
                      wsrc + (size_t)(seg >> 5) * IFF + (seg & 31) * 4);
        }
        cpasync16(buf + W_BYTES + tid * 16, xs + (size_t)c * XM_Q + tid);
        if (tid < XM_Q - 256)
            cpasync16(buf + W_BYTES + (tid + 256) * 16,
                      xs + (size_t)c * XM_Q + tid + 256);
        CP_COMMIT();
    };

    stage(0); stage(1); stage(2);

    for (int c = 0; c < MLP_C; c++) {
        pipeline_wait(MLP_C - 1 - c);
        __syncthreads();
        if (c + 3 < MLP_C) stage(c + 3);

        const char* buf = sm + (c & 3) * MSTG;
        const float4* wq = reinterpret_cast<const float4*>(buf);
        float4 w0 = wq[(wid * 4 + 0) * 32 + lane];
        float4 w1 = wq[(wid * 4 + 1) * 32 + lane];
        float4 w2 = wq[(wid * 4 + 2) * 32 + lane];
        float4 w3 = wq[(wid * 4 + 3) * 32 + lane];
        #pragma unroll
        for (int e = 0; e < 4; e++) {
            const ulonglong2* xp = reinterpret_cast<const ulonglong2*>(
                buf + W_BYTES + (lane * 13 + e * 3) * 16);
            ulonglong2 p0 = xp[0];
            ulonglong2 p1 = xp[1];
            ulonglong2 p2 = xp[2];
            unsigned long long d0d = fdup(getf(w0, e));
            unsigned long long d1d = fdup(getf(w1, e));
            unsigned long long d2d = fdup(getf(w2, e));
            unsigned long long d3d = fdup(getf(w3, e));
            ffma2(acc[0][0], d0d, p0.x); ffma2(acc[0][1], d0d, p0.y);
            ffma2(acc[0][2], d0d, p1.x); ffma2(acc[0][3], d0d, p1.y);
            ffma2(acc[0][4], d0d, p2.x); ffma2(acc[0][5], d0d, p2.y);
            ffma2(acc[1][0], d1d, p0.x); ffma2(acc[1][1], d1d, p0.y);
            ffma2(acc[1][2], d1d, p1.x); ffma2(acc[1][3], d1d, p1.y);
            ffma2(acc[1][4], d1d, p2.x); ffma2(acc[1][5], d1d, p2.y);
            ffma2(acc[2][0], d2d, p0.x); ffma2(acc[2][1], d2d, p0.y);
            ffma2(acc[2][2], d2d, p1.x); ffma2(acc[2][3], d2d, p1.y);
            ffma2(acc[2][4], d2d, p2.x); ffma2(acc[2][5], d2d, p2.y);
            ffma2(acc[3][0], d3d, p0.x); ffma2(acc[3][1], d3d, p0.y);
            ffma2(acc[3][2], d3d, p1.x); ffma2(acc[3][3], d3d, p1.y);
            ffma2(acc[3][4], d3d, p2.x); ffma2(acc[3][5], d3d, p2.y);
        }
    }

    // acc[r][q]: lo -> j=2q, hi -> j=2q+1; j=m*4+k; m: 0->gate(3),1->up(4),2->down(6)
    const int d0 = dt * 32 + wid * 4;
    #pragma unroll
    for (int q = 0; q < 6; q++) {
        #pragma unroll
        for (int r = 0; r < 4; r++) {
            float lo, hi;
            unpack2(acc[r][q], lo, hi);
            float vlo = wsum(lo);
            float vhi = wsum(hi);
            #pragma unroll
            for (int h = 0; h < 2; h++) {
                const int j = 2 * q + h;
                const int m = j >> 2;
                const int k = j & 3;
                const int mod = (m == 0) ? 3 : (m == 1) ? 4 : 6;
                const int rowb = (l * 7 + mod) * 8 + 4 + k;
                const float v = h ? vhi : vlo;
                if (lane == ((j * 4 + r) & 31))
                    out[(size_t)rowb * DM + d0 + r] = v;
            }
        }
    }
}

// ---- Affine module (q/k/v/o): 4 RHS; 256 thr, 8 warps x 4 rows = 32 rows ----
template <int C>
__device__ void affine_block(const float4* __restrict__ xt,
                             const float* __restrict__ W,
                             float* __restrict__ out,
                             int l, int dt, int mod,
                             char* sm, uint32_t smem_u,
                             int tid, int lane, int wid)
{
    const int I = C * KCH;
    const float* Wg = W + ((size_t)l * DM + dt * 32) * I;
    const float4* xs = xt + (size_t)l * C * XA_Q;

    unsigned long long acc[4][2];
    #pragma unroll
    for (int r = 0; r < 4; r++) { acc[r][0] = 0ull; acc[r][1] = 0ull; }

    auto stage = [&](int c) {
        const uint32_t buf = smem_u + (c & 3) * ASTG;
        const float* wsrc = Wg + c * KCH;
        #pragma unroll
        for (int s = 0; s < 4; s++) {
            const int seg = tid + s * 256;
            cpasync16(buf + seg * 16,
                      wsrc + (size_t)(seg >> 5) * I + (seg & 31) * 4);
        }
        if (tid < XA_Q)
            cpasync16(buf + W_BYTES + tid * 16, xs + (size_t)c * XA_Q + tid);
        CP_COMMIT();
    };

    const int F = (C < 3) ? C : 3;
    for (int s = 0; s < F; s++) stage(s);

    for (int c = 0; c < C; c++) {
        pipeline_wait(C - 1 - c);
        __syncthreads();
        if (c + 3 < C) stage(c + 3);

        const char* buf = sm + (c & 3) * ASTG;
        const float4* wq = reinterpret_cast<const float4*>(buf);
        float4 w0 = wq[(wid * 4 + 0) * 32 + lane];
        float4 w1 = wq[(wid * 4 + 1) * 32 + lane];
        float4 w2 = wq[(wid * 4 + 2) * 32 + lane];
        float4 w3 = wq[(wid * 4 + 3) * 32 + lane];
        #pragma unroll
        for (int e = 0; e < 4; e++) {
            ulonglong2 xv = *reinterpret_cast<const ulonglong2*>(
                buf + W_BYTES + (lane * 5 + e) * 16);
            unsigned long long d0d = fdup(getf(w0, e));
            unsigned long long d1d = fdup(getf(w1, e));
            unsigned long long d2d = fdup(getf(w2, e));
            unsigned long long d3d = fdup(getf(w3, e));
            ffma2(acc[0][0], d0d, xv.x); ffma2(acc[0][1], d0d, xv.y);
            ffma2(acc[1][0], d1d, xv.x); ffma2(acc[1][1], d1d, xv.y);
            ffma2(acc[2][0], d2d, xv.x); ffma2(acc[2][1], d2d, xv.y);
            ffma2(acc[3][0], d3d, xv.x); ffma2(acc[3][1], d3d, xv.y);
        }
    }

    const int d0 = dt * 32 + wid * 4;
    const int rowb = (l * 7 + mod) * 8 + 4;
    #pragma unroll
    for (int r = 0; r < 4; r++)
        #pragma unroll
        for (int q = 0; q < 2; q++) {
            float lo, hi;
            unpack2(acc[r][q], lo, hi);
            float vlo = wsum(lo);
            float vhi = wsum(hi);
            const int k0 = 2 * q, k1 = 2 * q + 1;
            if (lane == (r * 4 + k0)) out[(size_t)(rowb + k0) * DM + d0 + r] = vlo;
            if (lane == (r * 4 + k1)) out[(size_t)(rowb + k1) * DM + d0 + r] = vhi;
        }
}

#define NCOPY 64

__global__ __launch_bounds__(256, 2)
void bse_fused_kernel(const float* __restrict__ residual,
                      const float* __restrict__ Wq,
                      const float* __restrict__ Wk,
                      const float* __restrict__ Wv,
                      const float* __restrict__ Wo,
                      const float* __restrict__ Wd,
                      float* __restrict__ out)
{
    extern __shared__ __align__(16) char sm[];
    const int bid = blockIdx.x;
    const int tid = threadIdx.x;
    const int lane = tid & 31;
    const int wid = tid >> 5;
    const uint32_t smem_u = (uint32_t)__cvta_generic_to_shared(sm);

    if (bid < 1024) {
        mlp_block(Wd, out, bid >> 5, bid & 31, sm, smem_u, tid, lane, wid);
    } else if (bid < 1024 + NCOPY) {
        // Residual copy: residual[l,mod,k,:] -> out row (g*8 + k)
        const float4* src = reinterpret_cast<const float4*>(residual);
        float4* dst = reinterpret_cast<float4*>(out);
        const int n = NL * 7 * NK * (DM / 4);          // 229376 float4
        #pragma unroll 4
        for (int e = (bid - 1024) * 256 + tid; e < n; e += NCOPY * 256) {
            const int d = e & 255;
            const int k = (e >> 8) & 3;
            const int g = e >> 10;
            dst[(size_t)(g * 8 + k) * 256 + d] = __ldcs(src + e);
        }
    } else if (bid < 2048 + NCOPY) {
        const int a = bid - (1024 + NCOPY);
        affine_block<QO_C>(g_xt_q, Wq, out, a >> 5, a & 31, 0, sm, smem_u, tid, lane, wid);
    } else if (bid < 3072 + NCOPY) {
        const int a = bid - (2048 + NCOPY);
        affine_block<QO_C>(g_xt_o, Wo, out, a >> 5, a & 31, 5, sm, smem_u, tid, lane, wid);
    } else if (bid < 4096 + NCOPY) {
        const int a = bid - (3072 + NCOPY);
        affine_block<KV_C>(g_xt_k, Wk, out, a >> 5, a & 31, 1, sm, smem_u, tid, lane, wid);
    } else {
        const int a = bid - (4096 + NCOPY);
        affine_block<KV_C>(g_xt_v, Wv, out, a >> 5, a & 31, 2, sm, smem_u, tid, lane, wid);
    }
}

extern "C" void kernel_launch(void* const* d_in, const int* in_sizes, int n_in,
                              void* d_out, int out_size)
{
    (void)in_sizes; (void)n_in; (void)out_size;
    const float* residual = (const float*)d_in[0];
    const float* cq = (const float*)d_in[1];
    const float* ck = (const float*)d_in[2];
    const float* cv = (const float*)d_in[3];
    const float* co = (const float*)d_in[4];
    const float* cm = (const float*)d_in[5];
    const float* Wq = (const float*)d_in[6];
    const float* Wk = (const float*)d_in[7];
    const float* Wv = (const float*)d_in[8];
    const float* Wo = (const float*)d_in[9];
    const float* Wd = (const float*)d_in[10];
    float* out = (float*)d_out;

    static bool attr_done = false;
    if (!attr_done) {
        cudaFuncSetAttribute(bse_fused_kernel,
                             cudaFuncAttributeMaxDynamicSharedMemorySize, SMEM_BYTES);
        attr_done = true;
    }

    transpose_x_kernel<<<256, 256>>>(cq, ck, cv, co, cm);
    bse_fused_kernel<<<5120 + NCOPY, 256, SMEM_BYTES>>>(residual,
                                                        Wq, Wk, Wv, Wo, Wd, out);
}